// round 16
// baseline (speedup 1.0000x reference)
#include <cuda_runtime.h>
#include <cuda_bf16.h>
#include <math.h>
#include <stdint.h>

#define BN 8192
#define CN 128
#define NL 8
#define BC (BN*CN)
#define SLICE (BC*8)
#define AMU_SIZE (BN*32)
#define EPSF 1e-6f
#define KL 160
#define SAL 88
#define SW 40    // A-chunk SMEM row stride (bf16)
#define SB 136   // resident-B SMEM row stride (bf16)

// ------------------------- device scratch -------------------------
__device__ __nv_bfloat16 g_feats_hi[BN*KL];
__device__ __nv_bfloat16 g_feats_lo[BN*KL];
__device__ __nv_bfloat16 g_LW_hi[1024*KL];
__device__ __nv_bfloat16 g_LW_lo[1024*KL];
__device__ __nv_bfloat16 g_Wb_hi[NL*8*CN*CN];   // [l][kb][o][i]
__device__ __nv_bfloat16 g_Wb_lo[NL*8*CN*CN];
__device__ float g_rotM[NL*64*CN];
__device__ float g_h[BC*8];
__device__ float g_res[BC*8];
__device__ __nv_bfloat16 g_act_hi[8*BC];
__device__ __nv_bfloat16 g_act_lo[8*BC];
__device__ float g_gout[8*BC];

__device__ const int c_blades[8] = {0,1,2,4,3,5,6,7};

__device__ __forceinline__ int cl_sign(int a, int b) {
    int s = 0; int aa = a >> 1;
    while (aa) { s += __popc(aa & b); aa >>= 1; }
    return (s & 1) ? -1 : 1;
}

__device__ __forceinline__ uint32_t smem_u32(const void* p) {
    uint32_t a;
    asm("{ .reg .u64 t; cvta.to.shared.u64 t, %1; cvt.u32.u64 %0, t; }" : "=r"(a) : "l"(p));
    return a;
}

__device__ __forceinline__ void cp16(uint32_t dst, const void* src) {
    asm volatile("cp.async.cg.shared.global [%0], [%1], 16;" :: "r"(dst), "l"(src));
}

__device__ __forceinline__ void mma16816(float* c, const uint32_t* a, const uint32_t* b) {
    asm volatile("mma.sync.aligned.m16n8k16.row.col.f32.bf16.bf16.f32 "
        "{%0,%1,%2,%3}, {%4,%5,%6,%7}, {%8,%9}, {%0,%1,%2,%3};"
        : "+f"(c[0]), "+f"(c[1]), "+f"(c[2]), "+f"(c[3])
        : "r"(a[0]), "r"(a[1]), "r"(a[2]), "r"(a[3]), "r"(b[0]), "r"(b[1]));
}

// ------------------------- merged prep kernel -------------------------
#define PREP_REPACK   4096
#define PREP_RLIFT    (PREP_REPACK + 640)
#define PREP_ROTOR    (PREP_RLIFT + 4)
#define PREP_TOTAL    (PREP_ROTOR + 1024)

__global__ void __launch_bounds__(256) prep_kernel(
    const float* __restrict__ linW, const float* __restrict__ liftW,
    const float* __restrict__ theta,
    const float* __restrict__ coords, const float* __restrict__ freq)
{
    int bid = blockIdx.x;
    if (bid < PREP_REPACK) {
        int n = bid * 256 + threadIdx.x;
        int i = n & 127;
        int o = (n >> 7) & 127;
        int kb = (n >> 14) & 7;
        int l = n >> 17;
        float w = linW[(size_t)(((l*128 + o)*128 + i) * 8) + kb];
        __nv_bfloat16 hi = __float2bfloat16(w);
        g_Wb_hi[n] = hi;
        g_Wb_lo[n] = __float2bfloat16(w - __bfloat162float(hi));
    } else if (bid < PREP_RLIFT) {
        int n = (bid - PREP_REPACK) * 256 + threadIdx.x;
        if (n < 1024*KL) {
            int k = n % KL;
            int o = n / KL;
            float w = (k < 132) ? liftW[(size_t)k*1024 + o] : 0.0f;
            __nv_bfloat16 hi = __float2bfloat16(w);
            g_LW_hi[n] = hi;
            g_LW_lo[n] = __float2bfloat16(w - __bfloat162float(hi));
        }
    } else if (bid < PREP_ROTOR) {
        int n = (bid - PREP_RLIFT) * 256 + threadIdx.x;
        if (n < NL * CN) {
            int l = n / CN, c = n % CN;
            const float* t = theta + n * 3;
            float ang = sqrtf(t[0]*t[0] + t[1]*t[1] + t[2]*t[2] + EPSF);
            float R[8] = {0,0,0,0,0,0,0,0};
            R[0] = cosf(ang);
            float s = sinf(ang) / ang;
            R[4] = s * t[0]; R[5] = s * t[1]; R[6] = s * t[2];
            float Rr[8];
            #pragma unroll
            for (int i = 0; i < 8; i++) Rr[i] = (i >= 4) ? -R[i] : R[i];
            float M[64];
            #pragma unroll
            for (int i = 0; i < 64; i++) M[i] = 0.0f;
            const int iv[4] = {0, 4, 5, 6};
            for (int ii = 0; ii < 4; ii++) {
                int i = iv[ii]; float Ri = R[i]; int a = c_blades[i];
                for (int j = 0; j < 8; j++) {
                    int bb = c_blades[j];
                    int m_mask = a ^ bb;
                    float tj = Ri * (float)cl_sign(a, bb);
                    for (int pp = 0; pp < 4; pp++) {
                        int p = iv[pp]; int pm = c_blades[p];
                        int k_mask = m_mask ^ pm;
                        float s2 = (float)cl_sign(m_mask, pm);
                        int k = c_blades[k_mask];
                        M[j*8 + k] += tj * Rr[p] * s2;
                    }
                }
            }
            float* out = g_rotM + (size_t)l*64*CN + c;
            #pragma unroll
            for (int i = 0; i < 64; i++) out[(size_t)i*CN] = M[i];
        }
    } else {
        int gid = (bid - PREP_ROTOR) * 256 + threadIdx.x;
        int row = gid >> 5, lane = gid & 31;
        if (row >= BN) return;
        float c0 = coords[row*4+0], c1 = coords[row*4+1];
        float c2 = coords[row*4+2], c3 = coords[row*4+3];
        __nv_bfloat16* oh = g_feats_hi + (size_t)row * KL;
        __nv_bfloat16* ol = g_feats_lo + (size_t)row * KL;
        if (lane < 4) {
            float v = coords[row*4 + lane];
            __nv_bfloat16 hi = __float2bfloat16(v);
            oh[lane] = hi; ol[lane] = __float2bfloat16(v - __bfloat162float(hi));
        }
        #pragma unroll
        for (int f = lane; f < 64; f += 32) {
            float p = c0*freq[f] + c1*freq[64+f] + c2*freq[128+f] + c3*freq[192+f];
            float sv = sinf(p), cv = cosf(p);
            __nv_bfloat16 sh = __float2bfloat16(sv);
            __nv_bfloat16 ch = __float2bfloat16(cv);
            oh[4 + f]  = sh; ol[4 + f]  = __float2bfloat16(sv - __bfloat162float(sh));
            oh[68 + f] = ch; ol[68 + f] = __float2bfloat16(cv - __bfloat162float(ch));
        }
        if (lane < 28) {
            oh[132 + lane] = __float2bfloat16(0.0f);
            ol[132 + lane] = __float2bfloat16(0.0f);
        }
    }
}

// ------------------------- lift GEMM via mma -------------------------
__global__ void __launch_bounds__(256, 2) lift_mma(const float* __restrict__ liftb) {
    extern __shared__ __nv_bfloat16 sm[];
    __nv_bfloat16* sAhi = sm;
    __nv_bfloat16* sAlo = sm + 128*SAL;
    __nv_bfloat16* sBhi = sm + 2*128*SAL;
    __nv_bfloat16* sBlo = sm + 3*128*SAL;

    int tid = threadIdx.x;
    int wid = tid >> 5, lane = tid & 31;
    int group = lane >> 2, tig = lane & 3;
    int m_warp = (wid & 3) * 32;
    int n_warp = (wid >> 2) * 64;

    int nb = blockIdx.x << 7;
    int mb = blockIdx.y << 7;

    const __nv_bfloat16* Ahi = g_feats_hi + (size_t)mb*KL;
    const __nv_bfloat16* Alo = g_feats_lo + (size_t)mb*KL;
    const __nv_bfloat16* Bhi = g_LW_hi + (size_t)nb*KL;
    const __nv_bfloat16* Blo = g_LW_lo + (size_t)nb*KL;

    float acc[2][8][4];
    #pragma unroll
    for (int f = 0; f < 2; f++)
        #pragma unroll
        for (int g = 0; g < 8; g++)
            #pragma unroll
            for (int q = 0; q < 4; q++) acc[f][g][q] = 0.0f;

    #pragma unroll
    for (int chunk = 0; chunk < 2; chunk++) {
        int kc = chunk * 80;
        #pragma unroll
        for (int i = 0; i < 5; i++) {
            int idx = tid + 256*i;
            int row = idx / 10, ch = idx % 10;
            size_t src = (size_t)row*KL + kc + ch*8;
            int dst = row*SAL + ch*8;
            *(uint4*)&sAhi[dst] = *(const uint4*)&Ahi[src];
            *(uint4*)&sAlo[dst] = *(const uint4*)&Alo[src];
            *(uint4*)&sBhi[dst] = *(const uint4*)&Bhi[src];
            *(uint4*)&sBlo[dst] = *(const uint4*)&Blo[src];
        }
        __syncthreads();

        #pragma unroll
        for (int ks = 0; ks < 5; ks++) {
            int k0 = ks * 16;
            uint32_t ahi[2][4], alo[2][4];
            #pragma unroll
            for (int f = 0; f < 2; f++) {
                int r0 = (m_warp + f*16 + group) * SAL + k0 + tig*2;
                int r8 = r0 + 8*SAL;
                ahi[f][0] = *(const uint32_t*)&sAhi[r0];
                ahi[f][1] = *(const uint32_t*)&sAhi[r8];
                ahi[f][2] = *(const uint32_t*)&sAhi[r0 + 8];
                ahi[f][3] = *(const uint32_t*)&sAhi[r8 + 8];
                alo[f][0] = *(const uint32_t*)&sAlo[r0];
                alo[f][1] = *(const uint32_t*)&sAlo[r8];
                alo[f][2] = *(const uint32_t*)&sAlo[r0 + 8];
                alo[f][3] = *(const uint32_t*)&sAlo[r8 + 8];
            }
            #pragma unroll
            for (int g = 0; g < 8; g++) {
                int nrow = (n_warp + g*8 + group) * SAL + k0 + tig*2;
                uint32_t bhi[2], blo[2];
                bhi[0] = *(const uint32_t*)&sBhi[nrow];
                bhi[1] = *(const uint32_t*)&sBhi[nrow + 8];
                blo[0] = *(const uint32_t*)&sBlo[nrow];
                blo[1] = *(const uint32_t*)&sBlo[nrow + 8];
                #pragma unroll
                for (int f = 0; f < 2; f++) {
                    mma16816(acc[f][g], ahi[f], bhi);
                    mma16816(acc[f][g], ahi[f], blo);
                    mma16816(acc[f][g], alo[f], bhi);
                }
            }
        }
        __syncthreads();
    }

    #pragma unroll
    for (int f = 0; f < 2; f++) {
        #pragma unroll
        for (int g = 0; g < 8; g++) {
            int row = mb + m_warp + f*16 + group;
            int col = nb + n_warp + g*8 + tig*2;
            float b0 = liftb[col], b1 = liftb[col+1];
            float* p = g_h + (size_t)row*1024 + col;
            *(float2*)p = make_float2(acc[f][g][0] + b0, acc[f][g][1] + b1);
            *(float2*)(p + 8*1024) = make_float2(acc[f][g][2] + b0, acc[f][g][3] + b1);
        }
    }
}

// ------------------------- B-resident persistent blade GEMM (R14) -------------------------
#define PBF (128*SB)
#define PAC (128*SW)
#define ABASE (2*PBF)
#define ASTG (2*PAC)

__device__ __forceinline__ void loadA_chunk(
    const __nv_bfloat16* Ahi, const __nv_bfloat16* Alo,
    __nv_bfloat16* sm, int stage, int kc, int tid)
{
    __nv_bfloat16* base = sm + ABASE + stage*ASTG;
    #pragma unroll
    for (int e = 0; e < 2; e++) {
        int id = tid + 256*e;
        int r = id >> 2, kv = id & 3;
        int ko = kc + kv*8;
        int dst = r*SW + kv*8;
        cp16(smem_u32(base + dst),       Ahi + (size_t)r*128 + ko);
        cp16(smem_u32(base + PAC + dst), Alo + (size_t)r*128 + ko);
    }
    asm volatile("cp.async.commit_group;" ::: "memory");
}

__global__ void __launch_bounds__(256, 2) gemm_mma(int l) {
    extern __shared__ __nv_bfloat16 sm[];
    __nv_bfloat16* sBhi = sm;
    __nv_bfloat16* sBlo = sm + PBF;

    int tid = threadIdx.x;
    int wid = tid >> 5, lane = tid & 31;
    int group = lane >> 2, tig = lane & 3;
    int m_warp = (wid & 3) * 32;
    int n_warp = (wid >> 2) * 64;

    int mg = blockIdx.x;
    int kb = blockIdx.y;

    const __nv_bfloat16* Whi = g_Wb_hi + (size_t)(l*8 + kb)*CN*CN;
    const __nv_bfloat16* Wlo = g_Wb_lo + (size_t)(l*8 + kb)*CN*CN;
    const __nv_bfloat16* Ahi = g_act_hi + (size_t)kb*BC + (size_t)(mg*256)*128;
    const __nv_bfloat16* Alo = g_act_lo + (size_t)kb*BC + (size_t)(mg*256)*128;

    #pragma unroll
    for (int e = 0; e < 8; e++) {
        int id = tid + 256*e;
        int o = id >> 4, ch = id & 15;
        size_t src = (size_t)o*128 + ch*8;
        int dst = o*SB + ch*8;
        cp16(smem_u32(sBhi + dst), Whi + src);
        cp16(smem_u32(sBlo + dst), Wlo + src);
    }
    asm volatile("cp.async.commit_group;" ::: "memory");

    loadA_chunk(Ahi, Alo, sm, 0, 0,  tid);
    loadA_chunk(Ahi, Alo, sm, 1, 32, tid);

    float acc[2][8][4];
    #pragma unroll
    for (int f = 0; f < 2; f++)
        #pragma unroll
        for (int g = 0; g < 8; g++)
            #pragma unroll
            for (int q = 0; q < 4; q++) acc[f][g][q] = 0.0f;

    #pragma unroll
    for (int q = 0; q < 8; q++) {
        if (q < 7) asm volatile("cp.async.wait_group 1;" ::: "memory");
        else       asm volatile("cp.async.wait_group 0;" ::: "memory");
        __syncthreads();

        __nv_bfloat16* sAhi = sm + ABASE + (q & 1)*ASTG;
        __nv_bfloat16* sAlo = sAhi + PAC;
        int kc = (q & 3) * 32;

        #pragma unroll
        for (int ks = 0; ks < 2; ks++) {
            int k0 = ks * 16;
            uint32_t ahi[2][4], alo[2][4];
            #pragma unroll
            for (int f = 0; f < 2; f++) {
                int r0 = (m_warp + f*16 + group) * SW + k0 + tig*2;
                int r8 = r0 + 8*SW;
                ahi[f][0] = *(const uint32_t*)&sAhi[r0];
                ahi[f][1] = *(const uint32_t*)&sAhi[r8];
                ahi[f][2] = *(const uint32_t*)&sAhi[r0 + 8];
                ahi[f][3] = *(const uint32_t*)&sAhi[r8 + 8];
                alo[f][0] = *(const uint32_t*)&sAlo[r0];
                alo[f][1] = *(const uint32_t*)&sAlo[r8];
                alo[f][2] = *(const uint32_t*)&sAlo[r0 + 8];
                alo[f][3] = *(const uint32_t*)&sAlo[r8 + 8];
            }
            int kcol = kc + k0 + tig*2;
            #pragma unroll
            for (int g = 0; g < 8; g++) {
                int nrow = (n_warp + g*8 + group) * SB + kcol;
                uint32_t bhi[2], blo[2];
                bhi[0] = *(const uint32_t*)&sBhi[nrow];
                bhi[1] = *(const uint32_t*)&sBhi[nrow + 8];
                blo[0] = *(const uint32_t*)&sBlo[nrow];
                blo[1] = *(const uint32_t*)&sBlo[nrow + 8];
                #pragma unroll
                for (int f = 0; f < 2; f++) {
                    mma16816(acc[f][g], ahi[f], bhi);
                    mma16816(acc[f][g], ahi[f], blo);
                    mma16816(acc[f][g], alo[f], bhi);
                }
            }
        }
        __syncthreads();
        if (q < 6) {
            int qn = q + 2;
            loadA_chunk(Ahi + (qn >> 2) * (size_t)128*128,
                        Alo + (qn >> 2) * (size_t)128*128,
                        sm, q & 1, (qn & 3) * 32, tid);
        }

        if (q == 3 || q == 7) {
            int mb = mg*256 + (q >> 2)*128;
            float* gbase = g_gout + (size_t)kb*BC;
            #pragma unroll
            for (int f = 0; f < 2; f++) {
                #pragma unroll
                for (int g = 0; g < 8; g++) {
                    int row = mb + m_warp + f*16 + group;
                    int col = n_warp + g*8 + tig*2;
                    float* p = gbase + (size_t)row*128 + col;
                    *(float2*)p = make_float2(acc[f][g][0], acc[f][g][1]);
                    *(float2*)(p + 8*128) = make_float2(acc[f][g][2], acc[f][g][3]);
                    if (q == 3) {
                        acc[f][g][0] = 0.0f; acc[f][g][1] = 0.0f;
                        acc[f][g][2] = 0.0f; acc[f][g][3] = 0.0f;
                    }
                }
            }
        }
    }
}

// ------------------------- pointwise helpers (block variant, for ln_in + final) ------------
__device__ __forceinline__ void grade_inv(const float* x, float* inv, float (*sred)[4], int c) {
    float v[4];
    v[0] = x[0]*x[0];
    v[1] = x[1]*x[1] + x[2]*x[2] + x[3]*x[3];
    v[2] = x[4]*x[4] + x[5]*x[5] + x[6]*x[6];
    v[3] = x[7]*x[7];
    #pragma unroll
    for (int g = 0; g < 4; g++) {
        float t = v[g];
        t += __shfl_xor_sync(0xffffffffu, t, 16);
        t += __shfl_xor_sync(0xffffffffu, t, 8);
        t += __shfl_xor_sync(0xffffffffu, t, 4);
        t += __shfl_xor_sync(0xffffffffu, t, 2);
        t += __shfl_xor_sync(0xffffffffu, t, 1);
        if ((c & 31) == 0) sred[g][c >> 5] = t;
    }
    __syncthreads();
    #pragma unroll
    for (int g = 0; g < 4; g++)
        inv[g] = rsqrtf((sred[g][0]+sred[g][1]+sred[g][2]+sred[g][3]) * (1.0f/128.0f) + EPSF);
    __syncthreads();
}

__device__ __forceinline__ void ln_apply(float* x, const float* gamma, const float* inv, int c) {
    float f0 = gamma[c*4+0] * inv[0];
    float f1 = gamma[c*4+1] * inv[1];
    float f2 = gamma[c*4+2] * inv[2];
    float f3 = gamma[c*4+3] * inv[3];
    x[0] *= f0;
    x[1] *= f1; x[2] *= f1; x[3] *= f1;
    x[4] *= f2; x[5] *= f2; x[6] *= f2;
    x[7] *= f3;
}

__device__ __forceinline__ void rot_gelu_store(const float* x, const float* __restrict__ Mt,
                                               float alpha, int b, int c) {
    float y[8] = {0,0,0,0,0,0,0,0};
    #pragma unroll
    for (int j = 0; j < 8; j++) {
        float xj = x[j];
        #pragma unroll
        for (int k = 0; k < 8; k++)
            y[k] = fmaf(xj, __ldg(Mt + (size_t)(j*8+k)*CN + c), y[k]);
    }
    float nn = EPSF;
    #pragma unroll
    for (int k = 0; k < 8; k++) nn = fmaf(y[k], y[k], nn);
    float gate = 0.5f * (1.0f + erff(alpha * sqrtf(nn) * 0.70710678118654752f));
    #pragma unroll
    for (int k = 0; k < 8; k++) {
        float v = y[k] * gate;
        __nv_bfloat16 hi = __float2bfloat16(v);
        size_t idx = (size_t)k*BC + b*128 + c;
        g_act_hi[idx] = hi;
        g_act_lo[idx] = __float2bfloat16(v - __bfloat162float(hi));
    }
}

// ------------------------- input norm + layer-0 prologue -------------------------
__global__ void __launch_bounds__(256) ln_in_kernel(const float* __restrict__ in_gamma,
                                                    const float* __restrict__ ng0,
                                                    const float* __restrict__ alpha0) {
    __shared__ float sred[2][4][4];
    int row = threadIdx.x >> 7;
    int c = threadIdx.x & 127;
    int b = blockIdx.x * 2 + row;
    float x[8];
    const float* p = g_h + (size_t)(b*128 + c) * 8;
    *(float4*)x     = *(const float4*)p;
    *(float4*)(x+4) = *(const float4*)(p+4);

    float inv[4];
    grade_inv(x, inv, sred[row], c);
    ln_apply(x, in_gamma, inv, c);

    float* pr = g_res + (size_t)(b*128 + c) * 8;
    *(float4*)pr     = *(const float4*)x;
    *(float4*)(pr+4) = *(const float4*)(x+4);

    grade_inv(x, inv, sred[row], c);
    ln_apply(x, ng0, inv, c);
    rot_gelu_store(x, g_rotM, alpha0[c], b, c);
}

// ------------------------- warp-per-row inter-layer pointwise (layers 0..NL-2) -------------
__global__ void __launch_bounds__(256) ip_warp(const float* __restrict__ Mt_next,
                                               const float* __restrict__ linb,
                                               const float* __restrict__ resIn,
                                               float* __restrict__ outI,
                                               const float* __restrict__ gamma_next,
                                               const float* __restrict__ alpha_next) {
    int wid = threadIdx.x >> 5, lane = threadIdx.x & 31;
    int b = blockIdx.x * 8 + wid;
    int c0 = lane * 4;

    float x[4][8];
    // gout: blade-planar, coalesced float4 per plane
    #pragma unroll
    for (int kb = 0; kb < 8; kb++) {
        float4 v = *(const float4*)&g_gout[(size_t)kb*BC + (size_t)b*128 + c0];
        x[0][kb] = v.x; x[1][kb] = v.y; x[2][kb] = v.z; x[3][kb] = v.w;
    }
    // bias + residual + outI store
    #pragma unroll
    for (int cc = 0; cc < 4; cc++) {
        const float* lb = linb + (c0 + cc)*8;
        const float* rp = resIn + ((size_t)b*128 + c0 + cc)*8;
        float4 l0 = *(const float4*)lb,      l1 = *(const float4*)(lb + 4);
        float4 r0 = *(const float4*)rp,      r1 = *(const float4*)(rp + 4);
        x[cc][0] += l0.x + r0.x; x[cc][1] += l0.y + r0.y;
        x[cc][2] += l0.z + r0.z; x[cc][3] += l0.w + r0.w;
        x[cc][4] += l1.x + r1.x; x[cc][5] += l1.y + r1.y;
        x[cc][6] += l1.z + r1.z; x[cc][7] += l1.w + r1.w;
        float* po = outI + ((size_t)b*128 + c0 + cc)*8;
        *(float4*)po       = make_float4(x[cc][0], x[cc][1], x[cc][2], x[cc][3]);
        *(float4*)(po + 4) = make_float4(x[cc][4], x[cc][5], x[cc][6], x[cc][7]);
    }
    // grade sums, intra-warp only
    float s0 = 0.f, s1 = 0.f, s2 = 0.f, s3 = 0.f;
    #pragma unroll
    for (int cc = 0; cc < 4; cc++) {
        s0 += x[cc][0]*x[cc][0];
        s1 += x[cc][1]*x[cc][1] + x[cc][2]*x[cc][2] + x[cc][3]*x[cc][3];
        s2 += x[cc][4]*x[cc][4] + x[cc][5]*x[cc][5] + x[cc][6]*x[cc][6];
        s3 += x[cc][7]*x[cc][7];
    }
    #pragma unroll
    for (int m = 16; m >= 1; m >>= 1) {
        s0 += __shfl_xor_sync(0xffffffffu, s0, m);
        s1 += __shfl_xor_sync(0xffffffffu, s1, m);
        s2 += __shfl_xor_sync(0xffffffffu, s2, m);
        s3 += __shfl_xor_sync(0xffffffffu, s3, m);
    }
    float i0 = rsqrtf(s0*(1.0f/128.0f) + EPSF);
    float i1 = rsqrtf(s1*(1.0f/128.0f) + EPSF);
    float i2 = rsqrtf(s2*(1.0f/128.0f) + EPSF);
    float i3 = rsqrtf(s3*(1.0f/128.0f) + EPSF);
    // LN apply
    #pragma unroll
    for (int cc = 0; cc < 4; cc++) {
        float4 ga = *(const float4*)&gamma_next[(c0 + cc)*4];
        float f0 = ga.x * i0, f1 = ga.y * i1, f2 = ga.z * i2, f3 = ga.w * i3;
        x[cc][0] *= f0;
        x[cc][1] *= f1; x[cc][2] *= f1; x[cc][3] *= f1;
        x[cc][4] *= f2; x[cc][5] *= f2; x[cc][6] *= f2;
        x[cc][7] *= f3;
    }
    // rotor (vector over 4 consecutive channels)
    float y[4][8];
    #pragma unroll
    for (int cc = 0; cc < 4; cc++)
        #pragma unroll
        for (int k = 0; k < 8; k++) y[cc][k] = 0.0f;
    #pragma unroll
    for (int j = 0; j < 8; j++) {
        #pragma unroll
        for (int k = 0; k < 8; k++) {
            float4 m4 = *(const float4*)(Mt_next + (size_t)(j*8+k)*CN + c0);
            y[0][k] = fmaf(x[0][j], m4.x, y[0][k]);
            y[1][k] = fmaf(x[1][j], m4.y, y[1][k]);
            y[2][k] = fmaf(x[2][j], m4.z, y[2][k]);
            y[3][k] = fmaf(x[3][j], m4.w, y[3][k]);
        }
    }
    // gelu gate
    float4 al = *(const float4*)&alpha_next[c0];
    float av[4] = {al.x, al.y, al.z, al.w};
    #pragma unroll
    for (int cc = 0; cc < 4; cc++) {
        float nn = EPSF;
        #pragma unroll
        for (int k = 0; k < 8; k++) nn = fmaf(y[cc][k], y[cc][k], nn);
        float gate = 0.5f * (1.0f + erff(av[cc] * sqrtf(nn) * 0.70710678118654752f));
        #pragma unroll
        for (int k = 0; k < 8; k++) y[cc][k] *= gate;
    }
    // act stores: 4 bf16 per plane per thread (uint2)
    #pragma unroll
    for (int kb = 0; kb < 8; kb++) {
        __nv_bfloat16 hb[4], lb2[4];
        #pragma unroll
        for (int cc = 0; cc < 4; cc++) {
            float v = y[cc][kb];
            hb[cc] = __float2bfloat16(v);
            lb2[cc] = __float2bfloat16(v - __bfloat162float(hb[cc]));
        }
        size_t idx = (size_t)kb*BC + (size_t)b*128 + c0;
        *(uint2*)&g_act_hi[idx] = *(uint2*)hb;
        *(uint2*)&g_act_lo[idx] = *(uint2*)lb2;
    }
}

// ------------------------- final-layer pointwise (block variant + fused projection) --------
__global__ void __launch_bounds__(256) ip_final(const float* __restrict__ linb,
                                                const float* __restrict__ resIn,
                                                float* __restrict__ outI,
                                                const float* __restrict__ out_gamma,
                                                const float* __restrict__ projW,
                                                const float* __restrict__ projb,
                                                float* __restrict__ outA) {
    __shared__ float sred[2][4][4];
    __shared__ float sproj[8][12];
    int row = threadIdx.x >> 7;
    int c = threadIdx.x & 127;
    int b = blockIdx.x * 2 + row;
    float x[8];
    #pragma unroll
    for (int k = 0; k < 8; k++)
        x[k] = g_gout[(size_t)k*BC + b*128 + c] + linb[c*8 + k];

    const float* pr = resIn + (size_t)(b*128 + c) * 8;
    float r[8];
    *(float4*)r     = *(const float4*)pr;
    *(float4*)(r+4) = *(const float4*)(pr+4);
    #pragma unroll
    for (int k = 0; k < 8; k++) x[k] += r[k];

    float* po = outI + (size_t)(b*128 + c) * 8;
    *(float4*)po     = *(const float4*)x;
    *(float4*)(po+4) = *(const float4*)(x+4);

    float inv[4];
    grade_inv(x, inv, sred[row], c);
    ln_apply(x, out_gamma, inv, c);

    float p[12];
    #pragma unroll
    for (int o = 0; o < 4; o++)
        #pragma unroll
        for (int kk = 0; kk < 3; kk++)
            p[o*3+kk] = x[4+kk] * __ldg(projW + (size_t)(o*128 + c)*8 + 4 + kk);
    #pragma unroll
    for (int q = 0; q < 12; q++) {
        float t = p[q];
        t += __shfl_xor_sync(0xffffffffu, t, 16);
        t += __shfl_xor_sync(0xffffffffu, t, 8);
        t += __shfl_xor_sync(0xffffffffu, t, 4);
        t += __shfl_xor_sync(0xffffffffu, t, 2);
        t += __shfl_xor_sync(0xffffffffu, t, 1);
        p[q] = t;
    }
    int wp = threadIdx.x >> 5;
    if ((threadIdx.x & 31) == 0) {
        #pragma unroll
        for (int q = 0; q < 12; q++) sproj[wp][q] = p[q];
    }
    __syncthreads();
    int tid = threadIdx.x;
    if (tid < 64) {
        int rr = tid >> 5, j = tid & 31;
        int k = j & 7;
        int bb = blockIdx.x * 2 + rr;
        if (k < 4 || k > 6) outA[(size_t)bb*32 + j] = 0.0f;
    }
    if (tid < 24) {
        int rr = tid / 12, q = tid % 12;
        int o = q / 3, k = 4 + q % 3;
        int bb = blockIdx.x * 2 + rr;
        float s = sproj[rr*4+0][q] + sproj[rr*4+1][q] + sproj[rr*4+2][q] + sproj[rr*4+3][q];
        outA[(size_t)bb*32 + o*8 + k] = s + projb[o*8 + k];
    }
}

// ------------------------- launch -------------------------
extern "C" void kernel_launch(void* const* d_in, const int* in_sizes, int n_in,
                              void* d_out, int out_size) {
    const float* coords     = (const float*)d_in[0];
    const float* freq       = (const float*)d_in[1];
    const float* liftW      = (const float*)d_in[2];
    const float* liftb      = (const float*)d_in[3];
    const float* in_gamma   = (const float*)d_in[4];
    const float* norm_gamma = (const float*)d_in[5];
    const float* rotor_th   = (const float*)d_in[6];
    const float* act_alpha  = (const float*)d_in[7];
    const float* linW       = (const float*)d_in[8];
    const float* linb       = (const float*)d_in[9];
    const float* out_gamma  = (const float*)d_in[10];
    const float* projW      = (const float*)d_in[11];
    const float* projb      = (const float*)d_in[12];
    float* out = (float*)d_out;

    float* rotM_ptr;
    cudaGetSymbolAddress((void**)&rotM_ptr, g_rotM);
    float* res_ptr;
    cudaGetSymbolAddress((void**)&res_ptr, g_res);

    const int smem_lift = 4 * 128 * SAL * (int)sizeof(__nv_bfloat16);
    const int smem_gemm = (2*PBF + 2*ASTG) * (int)sizeof(__nv_bfloat16);
    cudaFuncSetAttribute(lift_mma, cudaFuncAttributeMaxDynamicSharedMemorySize, smem_lift);
    cudaFuncSetAttribute(gemm_mma, cudaFuncAttributeMaxDynamicSharedMemorySize, smem_gemm);

    prep_kernel<<<PREP_TOTAL, 256>>>(linW, liftW, rotor_th, coords, freq);
    lift_mma<<<dim3(8, BN/128), 256, smem_lift>>>(liftb);
    ln_in_kernel<<<BN/2, 256>>>(in_gamma, norm_gamma, act_alpha);

    for (int l = 0; l < NL; l++) {
        gemm_mma<<<dim3(32, 8), 256, smem_gemm>>>(l);
        const float* resIn = (l == 0) ? res_ptr : (out + AMU_SIZE + (size_t)(l-1)*SLICE);
        float* outI = out + AMU_SIZE + (size_t)l*SLICE;
        if (l < NL-1) {
            ip_warp<<<BN/8, 256>>>(rotM_ptr + (size_t)(l+1)*64*CN,
                                   linb + (size_t)l*CN*8,
                                   resIn, outI,
                                   norm_gamma + (size_t)(l+1)*CN*4,
                                   act_alpha + (size_t)(l+1)*CN);
        } else {
            ip_final<<<BN/2, 256>>>(linb + (size_t)l*CN*8, resIn, outI,
                                    out_gamma, projW, projb, out);
        }
    }
}

// round 17
// speedup vs baseline: 1.2348x; 1.2348x over previous
#include <cuda_runtime.h>
#include <cuda_bf16.h>
#include <math.h>
#include <stdint.h>

#define BN 8192
#define CN 128
#define NL 8
#define BC (BN*CN)
#define SLICE (BC*8)
#define AMU_SIZE (BN*32)
#define EPSF 1e-6f
#define KL 160
#define SAL 88
#define SW 40    // A-chunk SMEM row stride (bf16)
#define SB 136   // resident-B SMEM row stride (bf16)

// ------------------------- device scratch -------------------------
__device__ __nv_bfloat16 g_feats_hi[BN*KL];
__device__ __nv_bfloat16 g_feats_lo[BN*KL];
__device__ __nv_bfloat16 g_LW_hi[1024*KL];
__device__ __nv_bfloat16 g_LW_lo[1024*KL];
__device__ __nv_bfloat16 g_Wb_hi[NL*8*CN*CN];   // [l][kb][o][i]
__device__ __nv_bfloat16 g_Wb_lo[NL*8*CN*CN];
__device__ float g_rotM[NL*64*CN];
__device__ float g_h[BC*8];
__device__ float g_res[BC*8];
__device__ __nv_bfloat16 g_act_hi[8*BC];
__device__ __nv_bfloat16 g_act_lo[8*BC];
__device__ float g_gout[8*BC];

__device__ const int c_blades[8] = {0,1,2,4,3,5,6,7};

__device__ __forceinline__ int cl_sign(int a, int b) {
    int s = 0; int aa = a >> 1;
    while (aa) { s += __popc(aa & b); aa >>= 1; }
    return (s & 1) ? -1 : 1;
}

__device__ __forceinline__ uint32_t smem_u32(const void* p) {
    uint32_t a;
    asm("{ .reg .u64 t; cvta.to.shared.u64 t, %1; cvt.u32.u64 %0, t; }" : "=r"(a) : "l"(p));
    return a;
}

__device__ __forceinline__ void cp16(uint32_t dst, const void* src) {
    asm volatile("cp.async.cg.shared.global [%0], [%1], 16;" :: "r"(dst), "l"(src));
}

__device__ __forceinline__ void mma16816(float* c, const uint32_t* a, const uint32_t* b) {
    asm volatile("mma.sync.aligned.m16n8k16.row.col.f32.bf16.bf16.f32 "
        "{%0,%1,%2,%3}, {%4,%5,%6,%7}, {%8,%9}, {%0,%1,%2,%3};"
        : "+f"(c[0]), "+f"(c[1]), "+f"(c[2]), "+f"(c[3])
        : "r"(a[0]), "r"(a[1]), "r"(a[2]), "r"(a[3]), "r"(b[0]), "r"(b[1]));
}

// ------------------------- merged prep kernel -------------------------
#define PREP_REPACK   4096
#define PREP_RLIFT    (PREP_REPACK + 640)
#define PREP_ROTOR    (PREP_RLIFT + 4)
#define PREP_TOTAL    (PREP_ROTOR + 1024)

__global__ void __launch_bounds__(256) prep_kernel(
    const float* __restrict__ linW, const float* __restrict__ liftW,
    const float* __restrict__ theta,
    const float* __restrict__ coords, const float* __restrict__ freq)
{
    int bid = blockIdx.x;
    if (bid < PREP_REPACK) {
        int n = bid * 256 + threadIdx.x;
        int i = n & 127;
        int o = (n >> 7) & 127;
        int kb = (n >> 14) & 7;
        int l = n >> 17;
        float w = linW[(size_t)(((l*128 + o)*128 + i) * 8) + kb];
        __nv_bfloat16 hi = __float2bfloat16(w);
        g_Wb_hi[n] = hi;
        g_Wb_lo[n] = __float2bfloat16(w - __bfloat162float(hi));
    } else if (bid < PREP_RLIFT) {
        int n = (bid - PREP_REPACK) * 256 + threadIdx.x;
        if (n < 1024*KL) {
            int k = n % KL;
            int o = n / KL;
            float w = (k < 132) ? liftW[(size_t)k*1024 + o] : 0.0f;
            __nv_bfloat16 hi = __float2bfloat16(w);
            g_LW_hi[n] = hi;
            g_LW_lo[n] = __float2bfloat16(w - __bfloat162float(hi));
        }
    } else if (bid < PREP_ROTOR) {
        int n = (bid - PREP_RLIFT) * 256 + threadIdx.x;
        if (n < NL * CN) {
            int l = n / CN, c = n % CN;
            const float* t = theta + n * 3;
            float ang = sqrtf(t[0]*t[0] + t[1]*t[1] + t[2]*t[2] + EPSF);
            float R[8] = {0,0,0,0,0,0,0,0};
            R[0] = cosf(ang);
            float s = sinf(ang) / ang;
            R[4] = s * t[0]; R[5] = s * t[1]; R[6] = s * t[2];
            float Rr[8];
            #pragma unroll
            for (int i = 0; i < 8; i++) Rr[i] = (i >= 4) ? -R[i] : R[i];
            float M[64];
            #pragma unroll
            for (int i = 0; i < 64; i++) M[i] = 0.0f;
            const int iv[4] = {0, 4, 5, 6};
            for (int ii = 0; ii < 4; ii++) {
                int i = iv[ii]; float Ri = R[i]; int a = c_blades[i];
                for (int j = 0; j < 8; j++) {
                    int bb = c_blades[j];
                    int m_mask = a ^ bb;
                    float tj = Ri * (float)cl_sign(a, bb);
                    for (int pp = 0; pp < 4; pp++) {
                        int p = iv[pp]; int pm = c_blades[p];
                        int k_mask = m_mask ^ pm;
                        float s2 = (float)cl_sign(m_mask, pm);
                        int k = c_blades[k_mask];
                        M[j*8 + k] += tj * Rr[p] * s2;
                    }
                }
            }
            float* out = g_rotM + (size_t)l*64*CN + c;
            #pragma unroll
            for (int i = 0; i < 64; i++) out[(size_t)i*CN] = M[i];
        }
    } else {
        int gid = (bid - PREP_ROTOR) * 256 + threadIdx.x;
        int row = gid >> 5, lane = gid & 31;
        if (row >= BN) return;
        float c0 = coords[row*4+0], c1 = coords[row*4+1];
        float c2 = coords[row*4+2], c3 = coords[row*4+3];
        __nv_bfloat16* oh = g_feats_hi + (size_t)row * KL;
        __nv_bfloat16* ol = g_feats_lo + (size_t)row * KL;
        if (lane < 4) {
            float v = coords[row*4 + lane];
            __nv_bfloat16 hi = __float2bfloat16(v);
            oh[lane] = hi; ol[lane] = __float2bfloat16(v - __bfloat162float(hi));
        }
        #pragma unroll
        for (int f = lane; f < 64; f += 32) {
            float p = c0*freq[f] + c1*freq[64+f] + c2*freq[128+f] + c3*freq[192+f];
            float sv = sinf(p), cv = cosf(p);
            __nv_bfloat16 sh = __float2bfloat16(sv);
            __nv_bfloat16 ch = __float2bfloat16(cv);
            oh[4 + f]  = sh; ol[4 + f]  = __float2bfloat16(sv - __bfloat162float(sh));
            oh[68 + f] = ch; ol[68 + f] = __float2bfloat16(cv - __bfloat162float(ch));
        }
        if (lane < 28) {
            oh[132 + lane] = __float2bfloat16(0.0f);
            ol[132 + lane] = __float2bfloat16(0.0f);
        }
    }
}

// ------------------------- lift GEMM via mma -------------------------
__global__ void __launch_bounds__(256, 2) lift_mma(const float* __restrict__ liftb) {
    extern __shared__ __nv_bfloat16 sm[];
    __nv_bfloat16* sAhi = sm;
    __nv_bfloat16* sAlo = sm + 128*SAL;
    __nv_bfloat16* sBhi = sm + 2*128*SAL;
    __nv_bfloat16* sBlo = sm + 3*128*SAL;

    int tid = threadIdx.x;
    int wid = tid >> 5, lane = tid & 31;
    int group = lane >> 2, tig = lane & 3;
    int m_warp = (wid & 3) * 32;
    int n_warp = (wid >> 2) * 64;

    int nb = blockIdx.x << 7;
    int mb = blockIdx.y << 7;

    const __nv_bfloat16* Ahi = g_feats_hi + (size_t)mb*KL;
    const __nv_bfloat16* Alo = g_feats_lo + (size_t)mb*KL;
    const __nv_bfloat16* Bhi = g_LW_hi + (size_t)nb*KL;
    const __nv_bfloat16* Blo = g_LW_lo + (size_t)nb*KL;

    float acc[2][8][4];
    #pragma unroll
    for (int f = 0; f < 2; f++)
        #pragma unroll
        for (int g = 0; g < 8; g++)
            #pragma unroll
            for (int q = 0; q < 4; q++) acc[f][g][q] = 0.0f;

    #pragma unroll
    for (int chunk = 0; chunk < 2; chunk++) {
        int kc = chunk * 80;
        #pragma unroll
        for (int i = 0; i < 5; i++) {
            int idx = tid + 256*i;
            int row = idx / 10, ch = idx % 10;
            size_t src = (size_t)row*KL + kc + ch*8;
            int dst = row*SAL + ch*8;
            *(uint4*)&sAhi[dst] = *(const uint4*)&Ahi[src];
            *(uint4*)&sAlo[dst] = *(const uint4*)&Alo[src];
            *(uint4*)&sBhi[dst] = *(const uint4*)&Bhi[src];
            *(uint4*)&sBlo[dst] = *(const uint4*)&Blo[src];
        }
        __syncthreads();

        #pragma unroll
        for (int ks = 0; ks < 5; ks++) {
            int k0 = ks * 16;
            uint32_t ahi[2][4], alo[2][4];
            #pragma unroll
            for (int f = 0; f < 2; f++) {
                int r0 = (m_warp + f*16 + group) * SAL + k0 + tig*2;
                int r8 = r0 + 8*SAL;
                ahi[f][0] = *(const uint32_t*)&sAhi[r0];
                ahi[f][1] = *(const uint32_t*)&sAhi[r8];
                ahi[f][2] = *(const uint32_t*)&sAhi[r0 + 8];
                ahi[f][3] = *(const uint32_t*)&sAhi[r8 + 8];
                alo[f][0] = *(const uint32_t*)&sAlo[r0];
                alo[f][1] = *(const uint32_t*)&sAlo[r8];
                alo[f][2] = *(const uint32_t*)&sAlo[r0 + 8];
                alo[f][3] = *(const uint32_t*)&sAlo[r8 + 8];
            }
            #pragma unroll
            for (int g = 0; g < 8; g++) {
                int nrow = (n_warp + g*8 + group) * SAL + k0 + tig*2;
                uint32_t bhi[2], blo[2];
                bhi[0] = *(const uint32_t*)&sBhi[nrow];
                bhi[1] = *(const uint32_t*)&sBhi[nrow + 8];
                blo[0] = *(const uint32_t*)&sBlo[nrow];
                blo[1] = *(const uint32_t*)&sBlo[nrow + 8];
                #pragma unroll
                for (int f = 0; f < 2; f++) {
                    mma16816(acc[f][g], ahi[f], bhi);
                    mma16816(acc[f][g], ahi[f], blo);
                    mma16816(acc[f][g], alo[f], bhi);
                }
            }
        }
        __syncthreads();
    }

    #pragma unroll
    for (int f = 0; f < 2; f++) {
        #pragma unroll
        for (int g = 0; g < 8; g++) {
            int row = mb + m_warp + f*16 + group;
            int col = nb + n_warp + g*8 + tig*2;
            float b0 = liftb[col], b1 = liftb[col+1];
            float* p = g_h + (size_t)row*1024 + col;
            *(float2*)p = make_float2(acc[f][g][0] + b0, acc[f][g][1] + b1);
            *(float2*)(p + 8*1024) = make_float2(acc[f][g][2] + b0, acc[f][g][3] + b1);
        }
    }
}

// ------------------------- B-resident persistent blade GEMM -------------------------
#define PBF (128*SB)
#define PAC (128*SW)
#define ABASE (2*PBF)
#define ASTG (2*PAC)

__device__ __forceinline__ void loadA_chunk(
    const __nv_bfloat16* Ahi, const __nv_bfloat16* Alo,
    __nv_bfloat16* sm, int stage, int kc, int tid)
{
    __nv_bfloat16* base = sm + ABASE + stage*ASTG;
    #pragma unroll
    for (int e = 0; e < 2; e++) {
        int id = tid + 256*e;
        int r = id >> 2, kv = id & 3;
        int ko = kc + kv*8;
        int dst = r*SW + kv*8;
        cp16(smem_u32(base + dst),       Ahi + (size_t)r*128 + ko);
        cp16(smem_u32(base + PAC + dst), Alo + (size_t)r*128 + ko);
    }
    asm volatile("cp.async.commit_group;" ::: "memory");
}

__global__ void __launch_bounds__(256, 2) gemm_mma(int l) {
    extern __shared__ __nv_bfloat16 sm[];
    __nv_bfloat16* sBhi = sm;
    __nv_bfloat16* sBlo = sm + PBF;

    int tid = threadIdx.x;
    int wid = tid >> 5, lane = tid & 31;
    int group = lane >> 2, tig = lane & 3;
    int m_warp = (wid & 3) * 32;
    int n_warp = (wid >> 2) * 64;

    int mg = blockIdx.x;
    int kb = blockIdx.y;

    const __nv_bfloat16* Whi = g_Wb_hi + (size_t)(l*8 + kb)*CN*CN;
    const __nv_bfloat16* Wlo = g_Wb_lo + (size_t)(l*8 + kb)*CN*CN;
    const __nv_bfloat16* Ahi = g_act_hi + (size_t)kb*BC + (size_t)(mg*256)*128;
    const __nv_bfloat16* Alo = g_act_lo + (size_t)kb*BC + (size_t)(mg*256)*128;

    #pragma unroll
    for (int e = 0; e < 8; e++) {
        int id = tid + 256*e;
        int o = id >> 4, ch = id & 15;
        size_t src = (size_t)o*128 + ch*8;
        int dst = o*SB + ch*8;
        cp16(smem_u32(sBhi + dst), Whi + src);
        cp16(smem_u32(sBlo + dst), Wlo + src);
    }
    asm volatile("cp.async.commit_group;" ::: "memory");

    loadA_chunk(Ahi, Alo, sm, 0, 0,  tid);
    loadA_chunk(Ahi, Alo, sm, 1, 32, tid);

    float acc[2][8][4];
    #pragma unroll
    for (int f = 0; f < 2; f++)
        #pragma unroll
        for (int g = 0; g < 8; g++)
            #pragma unroll
            for (int q = 0; q < 4; q++) acc[f][g][q] = 0.0f;

    #pragma unroll
    for (int q = 0; q < 8; q++) {
        if (q < 7) asm volatile("cp.async.wait_group 1;" ::: "memory");
        else       asm volatile("cp.async.wait_group 0;" ::: "memory");
        __syncthreads();

        __nv_bfloat16* sAhi = sm + ABASE + (q & 1)*ASTG;
        __nv_bfloat16* sAlo = sAhi + PAC;
        int kc = (q & 3) * 32;

        #pragma unroll
        for (int ks = 0; ks < 2; ks++) {
            int k0 = ks * 16;
            uint32_t ahi[2][4], alo[2][4];
            #pragma unroll
            for (int f = 0; f < 2; f++) {
                int r0 = (m_warp + f*16 + group) * SW + k0 + tig*2;
                int r8 = r0 + 8*SW;
                ahi[f][0] = *(const uint32_t*)&sAhi[r0];
                ahi[f][1] = *(const uint32_t*)&sAhi[r8];
                ahi[f][2] = *(const uint32_t*)&sAhi[r0 + 8];
                ahi[f][3] = *(const uint32_t*)&sAhi[r8 + 8];
                alo[f][0] = *(const uint32_t*)&sAlo[r0];
                alo[f][1] = *(const uint32_t*)&sAlo[r8];
                alo[f][2] = *(const uint32_t*)&sAlo[r0 + 8];
                alo[f][3] = *(const uint32_t*)&sAlo[r8 + 8];
            }
            int kcol = kc + k0 + tig*2;
            #pragma unroll
            for (int g = 0; g < 8; g++) {
                int nrow = (n_warp + g*8 + group) * SB + kcol;
                uint32_t bhi[2], blo[2];
                bhi[0] = *(const uint32_t*)&sBhi[nrow];
                bhi[1] = *(const uint32_t*)&sBhi[nrow + 8];
                blo[0] = *(const uint32_t*)&sBlo[nrow];
                blo[1] = *(const uint32_t*)&sBlo[nrow + 8];
                #pragma unroll
                for (int f = 0; f < 2; f++) {
                    mma16816(acc[f][g], ahi[f], bhi);
                    mma16816(acc[f][g], ahi[f], blo);
                    mma16816(acc[f][g], alo[f], bhi);
                }
            }
        }
        __syncthreads();
        if (q < 6) {
            int qn = q + 2;
            loadA_chunk(Ahi + (qn >> 2) * (size_t)128*128,
                        Alo + (qn >> 2) * (size_t)128*128,
                        sm, q & 1, (qn & 3) * 32, tid);
        }

        if (q == 3 || q == 7) {
            int mb = mg*256 + (q >> 2)*128;
            float* gbase = g_gout + (size_t)kb*BC;
            #pragma unroll
            for (int f = 0; f < 2; f++) {
                #pragma unroll
                for (int g = 0; g < 8; g++) {
                    int row = mb + m_warp + f*16 + group;
                    int col = n_warp + g*8 + tig*2;
                    float* p = gbase + (size_t)row*128 + col;
                    *(float2*)p = make_float2(acc[f][g][0], acc[f][g][1]);
                    *(float2*)(p + 8*128) = make_float2(acc[f][g][2], acc[f][g][3]);
                    if (q == 3) {
                        acc[f][g][0] = 0.0f; acc[f][g][1] = 0.0f;
                        acc[f][g][2] = 0.0f; acc[f][g][3] = 0.0f;
                    }
                }
            }
        }
    }
}

// ------------------------- pointwise helpers -------------------------
__device__ __forceinline__ void grade_inv(const float* x, float* inv, float (*sred)[4], int c) {
    float v[4];
    v[0] = x[0]*x[0];
    v[1] = x[1]*x[1] + x[2]*x[2] + x[3]*x[3];
    v[2] = x[4]*x[4] + x[5]*x[5] + x[6]*x[6];
    v[3] = x[7]*x[7];
    #pragma unroll
    for (int g = 0; g < 4; g++) {
        float t = v[g];
        t += __shfl_xor_sync(0xffffffffu, t, 16);
        t += __shfl_xor_sync(0xffffffffu, t, 8);
        t += __shfl_xor_sync(0xffffffffu, t, 4);
        t += __shfl_xor_sync(0xffffffffu, t, 2);
        t += __shfl_xor_sync(0xffffffffu, t, 1);
        if ((c & 31) == 0) sred[g][c >> 5] = t;
    }
    __syncthreads();
    #pragma unroll
    for (int g = 0; g < 4; g++)
        inv[g] = rsqrtf((sred[g][0]+sred[g][1]+sred[g][2]+sred[g][3]) * (1.0f/128.0f) + EPSF);
    __syncthreads();
}

__device__ __forceinline__ void ln_apply(float* x, const float* gamma, const float* inv, int c) {
    float f0 = gamma[c*4+0] * inv[0];
    float f1 = gamma[c*4+1] * inv[1];
    float f2 = gamma[c*4+2] * inv[2];
    float f3 = gamma[c*4+3] * inv[3];
    x[0] *= f0;
    x[1] *= f1; x[2] *= f1; x[3] *= f1;
    x[4] *= f2; x[5] *= f2; x[6] *= f2;
    x[7] *= f3;
}

__device__ __forceinline__ void rot_gelu_store(const float* x, const float* __restrict__ Mt,
                                               float alpha, int b, int c) {
    float y[8] = {0,0,0,0,0,0,0,0};
    #pragma unroll
    for (int j = 0; j < 8; j++) {
        float xj = x[j];
        #pragma unroll
        for (int k = 0; k < 8; k++)
            y[k] = fmaf(xj, __ldg(Mt + (size_t)(j*8+k)*CN + c), y[k]);
    }
    float nn = EPSF;
    #pragma unroll
    for (int k = 0; k < 8; k++) nn = fmaf(y[k], y[k], nn);
    float gate = 0.5f * (1.0f + erff(alpha * sqrtf(nn) * 0.70710678118654752f));
    #pragma unroll
    for (int k = 0; k < 8; k++) {
        float v = y[k] * gate;
        __nv_bfloat16 hi = __float2bfloat16(v);
        size_t idx = (size_t)k*BC + b*128 + c;
        g_act_hi[idx] = hi;
        g_act_lo[idx] = __float2bfloat16(v - __bfloat162float(hi));
    }
}

// ------------------------- input norm + layer-0 prologue -------------------------
__global__ void __launch_bounds__(256) ln_in_kernel(const float* __restrict__ in_gamma,
                                                    const float* __restrict__ ng0,
                                                    const float* __restrict__ alpha0) {
    __shared__ float sred[2][4][4];
    int row = threadIdx.x >> 7;
    int c = threadIdx.x & 127;
    int b = blockIdx.x * 2 + row;
    float x[8];
    const float* p = g_h + (size_t)(b*128 + c) * 8;
    *(float4*)x     = *(const float4*)p;
    *(float4*)(x+4) = *(const float4*)(p+4);

    float inv[4];
    grade_inv(x, inv, sred[row], c);
    ln_apply(x, in_gamma, inv, c);

    float* pr = g_res + (size_t)(b*128 + c) * 8;
    *(float4*)pr     = *(const float4*)x;
    *(float4*)(pr+4) = *(const float4*)(x+4);

    grade_inv(x, inv, sred[row], c);
    ln_apply(x, ng0, inv, c);
    rot_gelu_store(x, g_rotM, alpha0[c], b, c);
}

// ------------------------- inter-layer pointwise (final layer fuses projection) ------------
__global__ void __launch_bounds__(256) ip_kernel(const float* __restrict__ Mt_next,
                                                 const float* __restrict__ linb,
                                                 const float* __restrict__ resIn,
                                                 float* __restrict__ outI,
                                                 const float* __restrict__ gamma_next,
                                                 const float* __restrict__ alpha_next,
                                                 const float* __restrict__ projW,
                                                 const float* __restrict__ projb,
                                                 float* __restrict__ outA,
                                                 int final_ln) {
    __shared__ float sred[2][4][4];
    __shared__ float sproj[8][12];
    int row = threadIdx.x >> 7;
    int c = threadIdx.x & 127;
    int b = blockIdx.x * 2 + row;
    float x[8];
    #pragma unroll
    for (int k = 0; k < 8; k++)
        x[k] = g_gout[(size_t)k*BC + b*128 + c] + linb[c*8 + k];

    const float* pr = resIn + (size_t)(b*128 + c) * 8;
    float r[8];
    *(float4*)r     = *(const float4*)pr;
    *(float4*)(r+4) = *(const float4*)(pr+4);
    #pragma unroll
    for (int k = 0; k < 8; k++) x[k] += r[k];

    float* po = outI + (size_t)(b*128 + c) * 8;
    *(float4*)po     = *(const float4*)x;
    *(float4*)(po+4) = *(const float4*)(x+4);

    float inv[4];
    grade_inv(x, inv, sred[row], c);
    ln_apply(x, gamma_next, inv, c);

    if (!final_ln) {
        rot_gelu_store(x, Mt_next, alpha_next[c], b, c);
    } else {
        float p[12];
        #pragma unroll
        for (int o = 0; o < 4; o++)
            #pragma unroll
            for (int kk = 0; kk < 3; kk++)
                p[o*3+kk] = x[4+kk] * __ldg(projW + (size_t)(o*128 + c)*8 + 4 + kk);
        #pragma unroll
        for (int q = 0; q < 12; q++) {
            float t = p[q];
            t += __shfl_xor_sync(0xffffffffu, t, 16);
            t += __shfl_xor_sync(0xffffffffu, t, 8);
            t += __shfl_xor_sync(0xffffffffu, t, 4);
            t += __shfl_xor_sync(0xffffffffu, t, 2);
            t += __shfl_xor_sync(0xffffffffu, t, 1);
            p[q] = t;
        }
        int wp = threadIdx.x >> 5;
        if ((threadIdx.x & 31) == 0) {
            #pragma unroll
            for (int q = 0; q < 12; q++) sproj[wp][q] = p[q];
        }
        __syncthreads();
        int tid = threadIdx.x;
        if (tid < 64) {
            int rr = tid >> 5, j = tid & 31;
            int k = j & 7;
            int bb = blockIdx.x * 2 + rr;
            if (k < 4 || k > 6) outA[(size_t)bb*32 + j] = 0.0f;
        }
        if (tid < 24) {
            int rr = tid / 12, q = tid % 12;
            int o = q / 3, k = 4 + q % 3;
            int bb = blockIdx.x * 2 + rr;
            float s = sproj[rr*4+0][q] + sproj[rr*4+1][q] + sproj[rr*4+2][q] + sproj[rr*4+3][q];
            outA[(size_t)bb*32 + o*8 + k] = s + projb[o*8 + k];
        }
    }
}

// ------------------------- launch -------------------------
extern "C" void kernel_launch(void* const* d_in, const int* in_sizes, int n_in,
                              void* d_out, int out_size) {
    const float* coords     = (const float*)d_in[0];
    const float* freq       = (const float*)d_in[1];
    const float* liftW      = (const float*)d_in[2];
    const float* liftb      = (const float*)d_in[3];
    const float* in_gamma   = (const float*)d_in[4];
    const float* norm_gamma = (const float*)d_in[5];
    const float* rotor_th   = (const float*)d_in[6];
    const float* act_alpha  = (const float*)d_in[7];
    const float* linW       = (const float*)d_in[8];
    const float* linb       = (const float*)d_in[9];
    const float* out_gamma  = (const float*)d_in[10];
    const float* projW      = (const float*)d_in[11];
    const float* projb      = (const float*)d_in[12];
    float* out = (float*)d_out;

    float* rotM_ptr;
    cudaGetSymbolAddress((void**)&rotM_ptr, g_rotM);
    float* res_ptr;
    cudaGetSymbolAddress((void**)&res_ptr, g_res);

    const int smem_lift = 4 * 128 * SAL * (int)sizeof(__nv_bfloat16);
    const int smem_gemm = (2*PBF + 2*ASTG) * (int)sizeof(__nv_bfloat16);
    cudaFuncSetAttribute(lift_mma, cudaFuncAttributeMaxDynamicSharedMemorySize, smem_lift);
    cudaFuncSetAttribute(gemm_mma, cudaFuncAttributeMaxDynamicSharedMemorySize, smem_gemm);

    prep_kernel<<<PREP_TOTAL, 256>>>(linW, liftW, rotor_th, coords, freq);
    lift_mma<<<dim3(8, BN/128), 256, smem_lift>>>(liftb);
    ln_in_kernel<<<BN/2, 256>>>(in_gamma, norm_gamma, act_alpha);

    for (int l = 0; l < NL; l++) {
        gemm_mma<<<dim3(32, 8), 256, smem_gemm>>>(l);
        int fin = (l == NL-1) ? 1 : 0;
        const float* gnext = fin ? out_gamma : (norm_gamma + (size_t)(l+1)*CN*4);
        const float* anext = fin ? act_alpha : (act_alpha + (size_t)(l+1)*CN);
        const float* resIn = (l == 0) ? res_ptr : (out + AMU_SIZE + (size_t)(l-1)*SLICE);
        ip_kernel<<<BN/2, 256>>>(rotM_ptr + (size_t)(fin ? 0 : (l+1))*64*CN,
                                 linb + (size_t)l*CN*8,
                                 resIn,
                                 out + AMU_SIZE + (size_t)l*SLICE,
                                 gnext, anext,
                                 projW, projb, out, fin);
    }
}